// round 6
// baseline (speedup 1.0000x reference)
#include <cuda_runtime.h>
#include <cuda_bf16.h>

// QuaternionPositionToMatrixLayer: x[B,7] f32 -> pose[B,3,4] f32
//   row: q0 q1 q2 q3 tx ty tz  ->  [R | t] (3x4, row-major)
//
// R5: input staged through SMEM (coalesced LDG.128). Output is computed
// REDUNDANTLY per coalesced element (thread t produces output float4s
// j*256+t), so stores go straight to gmem as contiguous STG.128 with a
// streaming (.cs) hint — no output SMEM round-trip, one less barrier,
// 24KB/block less L1 port traffic, L2 kept warm for the input.

constexpr int TPB = 256;                        // rows per block
constexpr int IN_F4_PER_TILE  = TPB * 7 / 4;    // 448 float4 input
constexpr int OUT_F4_PER_TILE = TPB * 12 / 4;   // 768 float4 output (3/thread)

__global__ void __launch_bounds__(TPB)
quat_pose_kernel(const float4* __restrict__ in4,
                 float4* __restrict__ out4,
                 int nrows)
{
    __shared__ float4 s_in4[IN_F4_PER_TILE];    // 7168 B

    const int block_row0 = blockIdx.x * TPB;
    const int tid = threadIdx.x;

    // ---- Phase 1: coalesced tile load (contiguous float4) ----
    {
        const long long in4_total = (long long)nrows * 7 / 4;
        const long long base4 = (long long)block_row0 * 7 / 4;
        #pragma unroll
        for (int i = tid; i < IN_F4_PER_TILE; i += TPB) {
            if (base4 + i < in4_total) {
                s_in4[i] = in4[base4 + i];
            }
        }
    }
    __syncthreads();

    // ---- Phase 2: compute per coalesced OUTPUT element, store direct ----
    const float* s_in = reinterpret_cast<const float*>(s_in4);
    const long long out4_total = (long long)nrows * 3;
    const long long obase4 = (long long)block_row0 * 3;

    #pragma unroll
    for (int j = 0; j < 3; j++) {
        const int e = j * TPB + tid;            // tile-local output float4 idx
        const long long g = obase4 + e;
        if (g < out4_total) {
            const int row  = e / 3;             // local row in [0,256)
            const int comp = e - row * 3;       // which matrix row (0..2)
            const float* p = s_in + row * 7;
            const float q0 = p[0];
            const float q1 = p[1];
            const float q2 = p[2];
            const float q3 = p[3];

            float4 r;
            if (comp == 0) {
                r.x = q0 * q0 + q1 * q1 - q2 * q2 - q3 * q3;
                r.y = 2.0f * q1 * q2 - 2.0f * q0 * q3;
                r.z = 2.0f * q1 * q3 + 2.0f * q0 * q2;
                r.w = p[4];
            } else if (comp == 1) {
                r.x = 2.0f * q1 * q2 + 2.0f * q0 * q3;
                r.y = q0 * q0 - q1 * q1 + q2 * q2 - q3 * q3;
                r.z = 2.0f * q2 * q3 - 2.0f * q0 * q1;
                r.w = p[5];
            } else {
                r.x = 2.0f * q1 * q3 - 2.0f * q0 * q2;
                r.y = 2.0f * q2 * q3 + 2.0f * q0 * q1;
                r.z = q0 * q0 - q1 * q1 - q2 * q2 + q3 * q3;
                r.w = p[6];
            }
            __stcs(&out4[g], r);                // streaming: evict-first in L2
        }
    }
}

extern "C" void kernel_launch(void* const* d_in, const int* in_sizes, int n_in,
                              void* d_out, int out_size)
{
    const float4* in4 = reinterpret_cast<const float4*>(d_in[0]);
    float4* out4 = reinterpret_cast<float4*>(d_out);

    const int n_floats = in_sizes[0];     // B * 7
    const int nrows = n_floats / 7;       // B (4,000,000)

    const int nblocks = (nrows + TPB - 1) / TPB;   // 15625 for B=4M
    quat_pose_kernel<<<nblocks, TPB>>>(in4, out4, nrows);
}